// round 14
// baseline (speedup 1.0000x reference)
#include <cuda_runtime.h>
#include <cuda_bf16.h>
#include <cstdint>

#define B_ROWS 16384
#define F_DIM  1024
#define C_COLS 1000
#define C_PAD  1024
#define NSTRIPS (B_ROWS / 128)        // 128
#define NTILES_X (C_PAD / 128)        // 8

// Scratch (static __device__ arrays allowed; no dynamic allocation)
__device__ __nv_bfloat16 g_Fb[(size_t)B_ROWS * F_DIM];   // normalized features, bf16
__device__ __nv_bfloat16 g_Pb[(size_t)C_PAD * F_DIM];    // normalized prototypes (padded), bf16
__device__ float g_rowsum[B_ROWS];
__device__ unsigned g_cnt[NSTRIPS];                      // per-strip completion counters

// ---------------------------------------------------------------------------
// Helpers (base-ISA only: cp.async, ldmatrix, bf16 mma.sync)
// ---------------------------------------------------------------------------
__device__ __forceinline__ uint32_t smem_u32(const void* p) {
    uint32_t a;
    asm("{ .reg .u64 t; cvta.to.shared.u64 t, %1; cvt.u32.u64 %0, t; }" : "=r"(a) : "l"(p));
    return a;
}
__device__ __forceinline__ void cp_async16(uint32_t dst, const void* src) {
    asm volatile("cp.async.cg.shared.global [%0], [%1], 16;" :: "r"(dst), "l"(src));
}
__device__ __forceinline__ void cp_commit() { asm volatile("cp.async.commit_group;" ::: "memory"); }

__device__ __forceinline__ void ldsm_x4(uint32_t& r0, uint32_t& r1, uint32_t& r2, uint32_t& r3,
                                        uint32_t addr) {
    asm volatile("ldmatrix.sync.aligned.m8n8.x4.shared.b16 {%0,%1,%2,%3}, [%4];"
                 : "=r"(r0), "=r"(r1), "=r"(r2), "=r"(r3) : "r"(addr));
}
__device__ __forceinline__ void mma_bf16(float* c, uint32_t a0, uint32_t a1, uint32_t a2,
                                         uint32_t a3, uint32_t b0, uint32_t b1) {
    asm volatile(
        "mma.sync.aligned.m16n8k16.row.col.f32.bf16.bf16.f32 "
        "{%0,%1,%2,%3}, {%4,%5,%6,%7}, {%8,%9}, {%0,%1,%2,%3};"
        : "+f"(c[0]), "+f"(c[1]), "+f"(c[2]), "+f"(c[3])
        : "r"(a0), "r"(a1), "r"(a2), "r"(a3), "r"(b0), "r"(b1));
}
__device__ __forceinline__ uint32_t packbf2(float lo, float hi) {
    __nv_bfloat162 h = __floats2bfloat162_rn(lo, hi);
    return *reinterpret_cast<uint32_t*>(&h);
}

// ---------------------------------------------------------------------------
// Kernel 1: merged L2-normalize (features then protos), one WARP per row.
// 8 float4 loads/lane (MLP=8), shuffle-only reduction, uint2 bf16 stores.
// Also zeroes g_rowsum and g_cnt for this launch.
// ---------------------------------------------------------------------------
#define NORM_ROWS (B_ROWS + C_PAD)           // 17408
__global__ void __launch_bounds__(256) norm_kernel(const float* __restrict__ feat,
                                                   const float* __restrict__ prot) {
    int gw = blockIdx.x * 8 + (threadIdx.x >> 5);
    int l = threadIdx.x & 31;

    const float* src;
    uint2* dst;
    if (gw < B_ROWS) {
        src = feat + (size_t)gw * F_DIM;
        dst = (uint2*)(g_Fb + (size_t)gw * F_DIM);
    } else {
        int row = gw - B_ROWS;               // 0..1023
        dst = (uint2*)(g_Pb + (size_t)row * F_DIM);
        if (row >= C_COLS) {                 // zero padding rows
            uint2 z = make_uint2(0u, 0u);
#pragma unroll
            for (int i = 0; i < 8; i++) dst[l + 32 * i] = z;
            return;
        }
        src = prot + (size_t)row * F_DIM;
    }

    const float4* rin = (const float4*)src;
    float4 v[8];
    float ss = 0.0f;
#pragma unroll
    for (int i = 0; i < 8; i++) v[i] = rin[l + 32 * i];
#pragma unroll
    for (int i = 0; i < 8; i++)
        ss += v[i].x * v[i].x + v[i].y * v[i].y + v[i].z * v[i].z + v[i].w * v[i].w;
#pragma unroll
    for (int o = 16; o; o >>= 1) ss += __shfl_xor_sync(0xffffffffu, ss, o);

    float sc = 1.0f / fmaxf(sqrtf(ss), 1e-12f);
#pragma unroll
    for (int i = 0; i < 8; i++) {
        uint2 w2;
        w2.x = packbf2(v[i].x * sc, v[i].y * sc);
        w2.y = packbf2(v[i].z * sc, v[i].w * sc);
        dst[l + 32 * i] = w2;
    }
    if (gw < B_ROWS && l == 0) {
        g_rowsum[gw] = 0.0f;
        if (gw < NSTRIPS) g_cnt[gw] = 0u;
    }
}

// ---------------------------------------------------------------------------
// Kernel 2: bf16 mma.sync GEMM, CTA 128x128, BK=64, 3-stage cp.async pipeline
// 110.6KB smem -> 2 CTAs/SM (16 warps/SM).
// 8 warps: wm = wid>>2 (0..1, 64 rows each), wn = wid&3 (0..3, 32 cols each)
// Epilogue: iso = |ds| * sqrt(max(1 - sim, 0)); direct store + row-sum atomics.
// FUSED FINALIZE: last CTA of each 128-row strip (threadfence-reduction
// pattern on g_cnt) rewrites the strip in place: out = -(iso + rowmean)/T.
// ---------------------------------------------------------------------------
#define STAGES 3
#define BK 64
#define KCHUNKS (F_DIM / BK)          // 16
#define PAD_BYTES 144                 // (64+8) bf16 per row
#define A_ST_BYTES (128 * PAD_BYTES)  // 18432
#define STAGE_BYTES (2 * A_ST_BYTES)  // 36864 (A then B)
#define GEMM_SMEM (STAGES * STAGE_BYTES)   // 110592 -> 2 CTAs/SM

__device__ __forceinline__ void load_tile(uint32_t base, int kc, int m0, int n0, int tid) {
    const char* fb = (const char*)g_Fb;
    const char* pb = (const char*)g_Pb;
    uint32_t st = base + (uint32_t)(kc % STAGES) * STAGE_BYTES;
#pragma unroll
    for (int it = 0; it < 4; it++) {
        int s = tid + it * 256;            // 0..1023
        int r = s >> 3, q = s & 7;
        cp_async16(st + (uint32_t)(r * PAD_BYTES + q * 16),
                   fb + (size_t)(m0 + r) * 2048 + (size_t)kc * 128 + q * 16);
    }
    uint32_t stB = st + A_ST_BYTES;
#pragma unroll
    for (int it = 0; it < 4; it++) {
        int s = tid + it * 256;
        int r = s >> 3, q = s & 7;
        cp_async16(stB + (uint32_t)(r * PAD_BYTES + q * 16),
                   pb + (size_t)(n0 + r) * 2048 + (size_t)kc * 128 + q * 16);
    }
    cp_commit();
}

__global__ void __launch_bounds__(256, 2) gemm_kernel(const float* __restrict__ ds,
                                                      const float* __restrict__ temp,
                                                      float* __restrict__ out) {
    extern __shared__ char smem_raw[];
    uint32_t base = smem_u32(smem_raw);
    __shared__ unsigned s_tail;

    int tid = threadIdx.x;
    int wid = tid >> 5, l = tid & 31;
    int wm = wid >> 2, wn = wid & 3;
    int m0 = blockIdx.y * 128, n0 = blockIdx.x * 128;

    float c[4][4][4];
#pragma unroll
    for (int i = 0; i < 4; i++)
#pragma unroll
        for (int j = 0; j < 4; j++)
#pragma unroll
            for (int k = 0; k < 4; k++) c[i][j][k] = 0.0f;

    // prologue: prefetch chunks 0, 1
    load_tile(base, 0, m0, n0, tid);
    load_tile(base, 1, m0, n0, tid);

    for (int kc = 0; kc < KCHUNKS; kc++) {
        if (kc < KCHUNKS - 1) asm volatile("cp.async.wait_group 1;" ::: "memory");
        else                  asm volatile("cp.async.wait_group 0;" ::: "memory");
        __syncthreads();

        if (kc + 2 < KCHUNKS) load_tile(base, kc + 2, m0, n0, tid);

        uint32_t st = base + (uint32_t)(kc % STAGES) * STAGE_BYTES;
        uint32_t aBase = st + (uint32_t)(wm * 64) * PAD_BYTES;
        uint32_t bBase = st + A_ST_BYTES + (uint32_t)(wn * 32) * PAD_BYTES;

        int g = l >> 3;          // 0..3
        int r8 = l & 7;
#pragma unroll
        for (int ks = 0; ks < 4; ks++) {
            uint32_t a[4][4];
#pragma unroll
            for (int mt = 0; mt < 4; mt++) {
                // lanes: g0 rows 0-7 k-lo | g1 rows 8-15 k-lo | g2 rows 0-7 k-hi | g3 rows 8-15 k-hi
                uint32_t addr = aBase + (uint32_t)((mt * 16 + (g & 1) * 8 + r8) * PAD_BYTES
                                                  + ks * 32 + (g >> 1) * 16);
                ldsm_x4(a[mt][0], a[mt][1], a[mt][2], a[mt][3], addr);
            }
            uint32_t b[4][2];
#pragma unroll
            for (int pair = 0; pair < 2; pair++) {
                // matrices: [ntile 2p, k-lo] [ntile 2p, k-hi] [ntile 2p+1, k-lo] [ntile 2p+1, k-hi]
                int ntile = pair * 2 + (g >> 1);
                uint32_t addr = bBase + (uint32_t)((ntile * 8 + r8) * PAD_BYTES
                                                  + ks * 32 + (g & 1) * 16);
                ldsm_x4(b[pair * 2][0], b[pair * 2][1], b[pair * 2 + 1][0], b[pair * 2 + 1][1], addr);
            }
#pragma unroll
            for (int mt = 0; mt < 4; mt++)
#pragma unroll
                for (int nt = 0; nt < 4; nt++)
                    mma_bf16(c[mt][nt], a[mt][0], a[mt][1], a[mt][2], a[mt][3],
                             b[nt][0], b[nt][1]);
        }
        __syncthreads();
    }

    // ---------------- epilogue (pass 1: iso + rowsum) ----------------
    float dsa = fabsf(__ldg(ds));
    float rs[4][2];
#pragma unroll
    for (int mt = 0; mt < 4; mt++) { rs[mt][0] = 0.0f; rs[mt][1] = 0.0f; }

#pragma unroll
    for (int mt = 0; mt < 4; mt++) {
        int mrow = m0 + wm * 64 + mt * 16 + (l >> 2);
#pragma unroll
        for (int nt = 0; nt < 4; nt++) {
            int col = n0 + wn * 32 + nt * 8 + 2 * (l & 3);
            float i0 = dsa * sqrtf(fmaxf(1.0f - c[mt][nt][0], 0.0f));
            float i1 = dsa * sqrtf(fmaxf(1.0f - c[mt][nt][1], 0.0f));
            float i2 = dsa * sqrtf(fmaxf(1.0f - c[mt][nt][2], 0.0f));
            float i3 = dsa * sqrtf(fmaxf(1.0f - c[mt][nt][3], 0.0f));
            if (col < C_COLS) {             // col even, C_COLS even -> col+1 valid too
                rs[mt][0] += i0 + i1;
                rs[mt][1] += i2 + i3;
                *(float2*)(out + (size_t)mrow * C_COLS + col) = make_float2(i0, i1);
                *(float2*)(out + (size_t)(mrow + 8) * C_COLS + col) = make_float2(i2, i3);
            }
        }
    }
    // reduce row sums over the 4 lanes sharing a row (xor 1, 2), then atomics
#pragma unroll
    for (int mt = 0; mt < 4; mt++) {
#pragma unroll
        for (int h = 0; h < 2; h++) {
            float v = rs[mt][h];
            v += __shfl_xor_sync(0xffffffffu, v, 1);
            v += __shfl_xor_sync(0xffffffffu, v, 2);
            if ((l & 3) == 0) {
                int mrow = m0 + wm * 64 + mt * 16 + (l >> 2) + h * 8;
                atomicAdd(&g_rowsum[mrow], v);
            }
        }
    }

    // ---------------- strip completion (threadfence reduction) ----------------
    __threadfence();             // order this thread's out-stores before the counter
    __syncthreads();             // all threads' stores/fences done
    if (tid == 0) {
        unsigned old = atomicAdd(&g_cnt[blockIdx.y], 1u);
        s_tail = (old == NTILES_X - 1) ? 1u : 0u;
    }
    __syncthreads();
    if (s_tail == 0u) return;    // not the last CTA of this strip

    // ---------------- fused finalize: out = -(iso + rowmean)/T ----------------
    // All 8 CTAs of this strip are done; their stores are L2-visible (fences)
    // and rowsum atomics are L2-resident. Read via __ldcg to bypass L1.
    __threadfence();
    float invt = 1.0f / __ldg(temp);
    for (int r = wid; r < 128; r += 8) {
        float mean = __ldcg(&g_rowsum[m0 + r]) * (1.0f / (float)C_COLS);
        float4* p = (float4*)(out + (size_t)(m0 + r) * C_COLS);
#pragma unroll 2
        for (int j = l; j < C_COLS / 4; j += 32) {
            float4 x = __ldcg(p + j);
            x.x = -(x.x + mean) * invt;
            x.y = -(x.y + mean) * invt;
            x.z = -(x.z + mean) * invt;
            x.w = -(x.w + mean) * invt;
            p[j] = x;
        }
    }
}

// ---------------------------------------------------------------------------
extern "C" void kernel_launch(void* const* d_in, const int* in_sizes, int n_in,
                              void* d_out, int out_size) {
    const float* feat = (const float*)d_in[0];
    const float* prot = (const float*)d_in[1];
    const float* ds   = (const float*)d_in[2];
    const float* temp = (const float*)d_in[3];
    float* out = (float*)d_out;

    cudaFuncSetAttribute(gemm_kernel, cudaFuncAttributeMaxDynamicSharedMemorySize, GEMM_SMEM);

    norm_kernel<<<NORM_ROWS / 8, 256>>>(feat, prot);
    gemm_kernel<<<dim3(NTILES_X, NSTRIPS), 256, GEMM_SMEM>>>(ds, temp, out);
}

// round 15
// speedup vs baseline: 1.2459x; 1.2459x over previous
#include <cuda_runtime.h>
#include <cuda_bf16.h>
#include <cstdint>

#define B_ROWS 16384
#define F_DIM  1024
#define C_COLS 1000
#define C_PAD  1024

// Scratch (static __device__ arrays allowed; no dynamic allocation)
__device__ __nv_bfloat16 g_Fb[(size_t)B_ROWS * F_DIM];   // normalized features, bf16
__device__ __nv_bfloat16 g_Pb[(size_t)C_PAD * F_DIM];    // normalized prototypes (padded), bf16
__device__ float g_rowsum[B_ROWS];

// ---------------------------------------------------------------------------
// Helpers (base-ISA only: cp.async, ldmatrix, bf16 mma.sync)
// ---------------------------------------------------------------------------
__device__ __forceinline__ uint32_t smem_u32(const void* p) {
    uint32_t a;
    asm("{ .reg .u64 t; cvta.to.shared.u64 t, %1; cvt.u32.u64 %0, t; }" : "=r"(a) : "l"(p));
    return a;
}
__device__ __forceinline__ void cp_async16(uint32_t dst, const void* src) {
    asm volatile("cp.async.cg.shared.global [%0], [%1], 16;" :: "r"(dst), "l"(src));
}
__device__ __forceinline__ void cp_commit() { asm volatile("cp.async.commit_group;" ::: "memory"); }

__device__ __forceinline__ void ldsm_x4(uint32_t& r0, uint32_t& r1, uint32_t& r2, uint32_t& r3,
                                        uint32_t addr) {
    asm volatile("ldmatrix.sync.aligned.m8n8.x4.shared.b16 {%0,%1,%2,%3}, [%4];"
                 : "=r"(r0), "=r"(r1), "=r"(r2), "=r"(r3) : "r"(addr));
}
__device__ __forceinline__ void mma_bf16(float* c, uint32_t a0, uint32_t a1, uint32_t a2,
                                         uint32_t a3, uint32_t b0, uint32_t b1) {
    asm volatile(
        "mma.sync.aligned.m16n8k16.row.col.f32.bf16.bf16.f32 "
        "{%0,%1,%2,%3}, {%4,%5,%6,%7}, {%8,%9}, {%0,%1,%2,%3};"
        : "+f"(c[0]), "+f"(c[1]), "+f"(c[2]), "+f"(c[3])
        : "r"(a0), "r"(a1), "r"(a2), "r"(a3), "r"(b0), "r"(b1));
}
__device__ __forceinline__ uint32_t packbf2(float lo, float hi) {
    __nv_bfloat162 h = __floats2bfloat162_rn(lo, hi);
    return *reinterpret_cast<uint32_t*>(&h);
}

// ---------------------------------------------------------------------------
// Kernel 1: merged L2-normalize (features then protos), one WARP per row.
// 8 float4 loads/lane (MLP=8), shuffle-only reduction, uint2 bf16 stores.
// ---------------------------------------------------------------------------
#define NORM_ROWS (B_ROWS + C_PAD)           // 17408
__global__ void __launch_bounds__(256) norm_kernel(const float* __restrict__ feat,
                                                   const float* __restrict__ prot) {
    int gw = blockIdx.x * 8 + (threadIdx.x >> 5);
    int l = threadIdx.x & 31;

    const float* src;
    uint2* dst;
    if (gw < B_ROWS) {
        src = feat + (size_t)gw * F_DIM;
        dst = (uint2*)(g_Fb + (size_t)gw * F_DIM);
    } else {
        int row = gw - B_ROWS;               // 0..1023
        dst = (uint2*)(g_Pb + (size_t)row * F_DIM);
        if (row >= C_COLS) {                 // zero padding rows
            uint2 z = make_uint2(0u, 0u);
#pragma unroll
            for (int i = 0; i < 8; i++) dst[l + 32 * i] = z;
            return;
        }
        src = prot + (size_t)row * F_DIM;
    }

    const float4* rin = (const float4*)src;
    float4 v[8];
    float ss = 0.0f;
#pragma unroll
    for (int i = 0; i < 8; i++) v[i] = rin[l + 32 * i];
#pragma unroll
    for (int i = 0; i < 8; i++)
        ss += v[i].x * v[i].x + v[i].y * v[i].y + v[i].z * v[i].z + v[i].w * v[i].w;
#pragma unroll
    for (int o = 16; o; o >>= 1) ss += __shfl_xor_sync(0xffffffffu, ss, o);

    float sc = 1.0f / fmaxf(sqrtf(ss), 1e-12f);
#pragma unroll
    for (int i = 0; i < 8; i++) {
        uint2 w2;
        w2.x = packbf2(v[i].x * sc, v[i].y * sc);
        w2.y = packbf2(v[i].z * sc, v[i].w * sc);
        dst[l + 32 * i] = w2;
    }
    if (gw < B_ROWS && l == 0) g_rowsum[gw] = 0.0f;
}

// ---------------------------------------------------------------------------
// Kernel 2: bf16 mma.sync GEMM, CTA 128x128 with 128 THREADS (4 warps),
// warp tile 64x64 (16 MAC/smem-byte), BK=64, 3-stage pipeline.
// 110.6KB smem -> 2 CTAs/SM (8 warps/SM from 2 independent CTAs).
// wm = wid>>1 (0..1, 64 rows), wn = wid&1 (0..1, 64 cols).
// Epilogue: iso = |ds| * sqrt(max(1 - sim, 0)); store + row-sum atomics.
// ---------------------------------------------------------------------------
#define STAGES 3
#define BK 64
#define KCHUNKS (F_DIM / BK)          // 16
#define PAD_BYTES 144                 // (64+8) bf16 per row
#define A_ST_BYTES (128 * PAD_BYTES)  // 18432
#define STAGE_BYTES (2 * A_ST_BYTES)  // 36864 (A then B)
#define GEMM_SMEM (STAGES * STAGE_BYTES)   // 110592 -> 2 CTAs/SM

__device__ __forceinline__ void load_tile(uint32_t base, int kc, int m0, int n0, int tid) {
    const char* fb = (const char*)g_Fb;
    const char* pb = (const char*)g_Pb;
    uint32_t st = base + (uint32_t)(kc % STAGES) * STAGE_BYTES;
    // A: 128 rows x 128B -> 1024 x 16B ops, 8 per thread (128 threads)
#pragma unroll
    for (int it = 0; it < 8; it++) {
        int s = tid + it * 128;            // 0..1023
        int r = s >> 3, q = s & 7;
        cp_async16(st + (uint32_t)(r * PAD_BYTES + q * 16),
                   fb + (size_t)(m0 + r) * 2048 + (size_t)kc * 128 + q * 16);
    }
    uint32_t stB = st + A_ST_BYTES;
#pragma unroll
    for (int it = 0; it < 8; it++) {
        int s = tid + it * 128;
        int r = s >> 3, q = s & 7;
        cp_async16(stB + (uint32_t)(r * PAD_BYTES + q * 16),
                   pb + (size_t)(n0 + r) * 2048 + (size_t)kc * 128 + q * 16);
    }
    cp_commit();
}

__global__ void __launch_bounds__(128, 2) gemm_kernel(const float* __restrict__ ds,
                                                      float* __restrict__ out) {
    extern __shared__ char smem_raw[];
    uint32_t base = smem_u32(smem_raw);

    int tid = threadIdx.x;
    int wid = tid >> 5, l = tid & 31;
    int wm = wid >> 1, wn = wid & 1;          // 2x2 warp grid, 64x64 tiles
    int m0 = blockIdx.y * 128, n0 = blockIdx.x * 128;

    float c[4][8][4];
#pragma unroll
    for (int i = 0; i < 4; i++)
#pragma unroll
        for (int j = 0; j < 8; j++)
#pragma unroll
            for (int k = 0; k < 4; k++) c[i][j][k] = 0.0f;

    int g = l >> 3;          // 0..3
    int r8 = l & 7;

    // prologue: prefetch chunks 0, 1
    load_tile(base, 0, m0, n0, tid);
    load_tile(base, 1, m0, n0, tid);

    for (int kc = 0; kc < KCHUNKS; kc++) {
        if (kc < KCHUNKS - 1) asm volatile("cp.async.wait_group 1;" ::: "memory");
        else                  asm volatile("cp.async.wait_group 0;" ::: "memory");
        __syncthreads();

        if (kc + 2 < KCHUNKS) load_tile(base, kc + 2, m0, n0, tid);

        uint32_t st = base + (uint32_t)(kc % STAGES) * STAGE_BYTES;
        uint32_t aBase = st + (uint32_t)(wm * 64) * PAD_BYTES;
        uint32_t bBase = st + A_ST_BYTES + (uint32_t)(wn * 64) * PAD_BYTES;

#pragma unroll
        for (int ks = 0; ks < 4; ks++) {
            uint32_t a[4][4];
#pragma unroll
            for (int mt = 0; mt < 4; mt++) {
                // lanes: g0 rows 0-7 k-lo | g1 rows 8-15 k-lo | g2 rows 0-7 k-hi | g3 rows 8-15 k-hi
                uint32_t addr = aBase + (uint32_t)((mt * 16 + (g & 1) * 8 + r8) * PAD_BYTES
                                                  + ks * 32 + (g >> 1) * 16);
                ldsm_x4(a[mt][0], a[mt][1], a[mt][2], a[mt][3], addr);
            }
            uint32_t b[8][2];
#pragma unroll
            for (int pair = 0; pair < 4; pair++) {
                // matrices: [ntile 2p, k-lo] [ntile 2p, k-hi] [ntile 2p+1, k-lo] [ntile 2p+1, k-hi]
                int ntile = pair * 2 + (g >> 1);
                uint32_t addr = bBase + (uint32_t)((ntile * 8 + r8) * PAD_BYTES
                                                  + ks * 32 + (g & 1) * 16);
                ldsm_x4(b[pair * 2][0], b[pair * 2][1], b[pair * 2 + 1][0], b[pair * 2 + 1][1], addr);
            }
#pragma unroll
            for (int mt = 0; mt < 4; mt++)
#pragma unroll
                for (int nt = 0; nt < 8; nt++)
                    mma_bf16(c[mt][nt], a[mt][0], a[mt][1], a[mt][2], a[mt][3],
                             b[nt][0], b[nt][1]);
        }
        __syncthreads();
    }

    // ---------------- epilogue ----------------
    float dsa = fabsf(__ldg(ds));
    float rs[4][2];
#pragma unroll
    for (int mt = 0; mt < 4; mt++) { rs[mt][0] = 0.0f; rs[mt][1] = 0.0f; }

#pragma unroll
    for (int mt = 0; mt < 4; mt++) {
        int mrow = m0 + wm * 64 + mt * 16 + (l >> 2);
#pragma unroll
        for (int nt = 0; nt < 8; nt++) {
            int col = n0 + wn * 64 + nt * 8 + 2 * (l & 3);
            float i0 = dsa * sqrtf(fmaxf(1.0f - c[mt][nt][0], 0.0f));
            float i1 = dsa * sqrtf(fmaxf(1.0f - c[mt][nt][1], 0.0f));
            float i2 = dsa * sqrtf(fmaxf(1.0f - c[mt][nt][2], 0.0f));
            float i3 = dsa * sqrtf(fmaxf(1.0f - c[mt][nt][3], 0.0f));
            if (col < C_COLS) {             // col even, C_COLS even -> col+1 valid too
                rs[mt][0] += i0 + i1;
                rs[mt][1] += i2 + i3;
                *(float2*)(out + (size_t)mrow * C_COLS + col) = make_float2(i0, i1);
                *(float2*)(out + (size_t)(mrow + 8) * C_COLS + col) = make_float2(i2, i3);
            }
        }
    }
    // reduce row sums over the 4 lanes sharing a row (xor 1, 2), then atomics
#pragma unroll
    for (int mt = 0; mt < 4; mt++) {
#pragma unroll
        for (int h = 0; h < 2; h++) {
            float v = rs[mt][h];
            v += __shfl_xor_sync(0xffffffffu, v, 1);
            v += __shfl_xor_sync(0xffffffffu, v, 2);
            if ((l & 3) == 0) {
                int mrow = m0 + wm * 64 + mt * 16 + (l >> 2) + h * 8;
                atomicAdd(&g_rowsum[mrow], v);
            }
        }
    }
}

// ---------------------------------------------------------------------------
// Kernel 3: logits = -(iso + rowmean)/T, 2 float4 per thread (MLP=2).
// ---------------------------------------------------------------------------
#define F4_PER_ROW (C_COLS / 4)              // 250
#define FIN_TOTAL  (B_ROWS * F4_PER_ROW)     // 4,096,000
#define FIN_HALF   (FIN_TOTAL / 2)           // 2,048,000

__global__ void __launch_bounds__(256) finalize_kernel(float* __restrict__ out,
                                                       const float* __restrict__ temp) {
    unsigned v0 = blockIdx.x * 256u + threadIdx.x;
    if (v0 >= (unsigned)FIN_HALF) return;
    unsigned v1 = v0 + (unsigned)FIN_HALF;
    float invt = 1.0f / __ldg(temp);

    unsigned r0 = v0 / (unsigned)F4_PER_ROW;
    unsigned r1 = v1 / (unsigned)F4_PER_ROW;
    float4 x0 = *(float4*)(out + (size_t)v0 * 4);
    float4 x1 = *(float4*)(out + (size_t)v1 * 4);
    float m0 = __ldg(&g_rowsum[r0]) * (1.0f / (float)C_COLS);
    float m1 = __ldg(&g_rowsum[r1]) * (1.0f / (float)C_COLS);

    x0.x = -(x0.x + m0) * invt;  x0.y = -(x0.y + m0) * invt;
    x0.z = -(x0.z + m0) * invt;  x0.w = -(x0.w + m0) * invt;
    x1.x = -(x1.x + m1) * invt;  x1.y = -(x1.y + m1) * invt;
    x1.z = -(x1.z + m1) * invt;  x1.w = -(x1.w + m1) * invt;

    *(float4*)(out + (size_t)v0 * 4) = x0;
    *(float4*)(out + (size_t)v1 * 4) = x1;
}

// ---------------------------------------------------------------------------
extern "C" void kernel_launch(void* const* d_in, const int* in_sizes, int n_in,
                              void* d_out, int out_size) {
    const float* feat = (const float*)d_in[0];
    const float* prot = (const float*)d_in[1];
    const float* ds   = (const float*)d_in[2];
    const float* temp = (const float*)d_in[3];
    float* out = (float*)d_out;

    cudaFuncSetAttribute(gemm_kernel, cudaFuncAttributeMaxDynamicSharedMemorySize, GEMM_SMEM);

    norm_kernel<<<NORM_ROWS / 8, 256>>>(feat, prot);
    gemm_kernel<<<dim3(C_PAD / 128, B_ROWS / 128), 128, GEMM_SMEM>>>(ds, out);
    finalize_kernel<<<(FIN_HALF + 255) / 256, 256>>>(out, temp);
}

// round 16
// speedup vs baseline: 1.3190x; 1.0586x over previous
#include <cuda_runtime.h>
#include <cuda_fp16.h>
#include <cstdint>

#define B_ROWS 16384
#define F_DIM  1024
#define C_COLS 1000
#define C_PAD  1024

// Scratch (static __device__ arrays allowed; no dynamic allocation)
__device__ __half g_Fb[(size_t)B_ROWS * F_DIM];   // normalized features, f16
__device__ __half g_Pb[(size_t)C_PAD * F_DIM];    // normalized prototypes (padded), f16
__device__ float g_rowsum[B_ROWS];

// ---------------------------------------------------------------------------
// Helpers (base-ISA only: cp.async, ldmatrix, f16 mma.sync)
// ---------------------------------------------------------------------------
__device__ __forceinline__ uint32_t smem_u32(const void* p) {
    uint32_t a;
    asm("{ .reg .u64 t; cvta.to.shared.u64 t, %1; cvt.u32.u64 %0, t; }" : "=r"(a) : "l"(p));
    return a;
}
__device__ __forceinline__ void cp_async16(uint32_t dst, const void* src) {
    asm volatile("cp.async.cg.shared.global [%0], [%1], 16;" :: "r"(dst), "l"(src));
}
__device__ __forceinline__ void cp_commit() { asm volatile("cp.async.commit_group;" ::: "memory"); }

__device__ __forceinline__ void ldsm_x4(uint32_t& r0, uint32_t& r1, uint32_t& r2, uint32_t& r3,
                                        uint32_t addr) {
    asm volatile("ldmatrix.sync.aligned.m8n8.x4.shared.b16 {%0,%1,%2,%3}, [%4];"
                 : "=r"(r0), "=r"(r1), "=r"(r2), "=r"(r3) : "r"(addr));
}
// f16 accumulate: D/C are 2x b32 regs (4 halves), same element mapping as f32.
__device__ __forceinline__ void mma_f16(uint32_t& c0, uint32_t& c1,
                                        uint32_t a0, uint32_t a1, uint32_t a2, uint32_t a3,
                                        uint32_t b0, uint32_t b1) {
    asm volatile(
        "mma.sync.aligned.m16n8k16.row.col.f16.f16.f16.f16 "
        "{%0,%1}, {%2,%3,%4,%5}, {%6,%7}, {%0,%1};"
        : "+r"(c0), "+r"(c1)
        : "r"(a0), "r"(a1), "r"(a2), "r"(a3), "r"(b0), "r"(b1));
}
__device__ __forceinline__ uint32_t packh2(float lo, float hi) {
    __half2 h = __floats2half2_rn(lo, hi);
    return *reinterpret_cast<uint32_t*>(&h);
}

// ---------------------------------------------------------------------------
// Kernel 1: merged L2-normalize (features then protos), one WARP per row.
// 8 float4 loads/lane (MLP=8), shuffle-only reduction, uint2 f16 stores.
// ---------------------------------------------------------------------------
#define NORM_ROWS (B_ROWS + C_PAD)           // 17408
__global__ void __launch_bounds__(256) norm_kernel(const float* __restrict__ feat,
                                                   const float* __restrict__ prot) {
    int gw = blockIdx.x * 8 + (threadIdx.x >> 5);
    int l = threadIdx.x & 31;

    const float* src;
    uint2* dst;
    if (gw < B_ROWS) {
        src = feat + (size_t)gw * F_DIM;
        dst = (uint2*)(g_Fb + (size_t)gw * F_DIM);
    } else {
        int row = gw - B_ROWS;               // 0..1023
        dst = (uint2*)(g_Pb + (size_t)row * F_DIM);
        if (row >= C_COLS) {                 // zero padding rows
            uint2 z = make_uint2(0u, 0u);
#pragma unroll
            for (int i = 0; i < 8; i++) dst[l + 32 * i] = z;
            return;
        }
        src = prot + (size_t)row * F_DIM;
    }

    const float4* rin = (const float4*)src;
    float4 v[8];
    float ss = 0.0f;
#pragma unroll
    for (int i = 0; i < 8; i++) v[i] = rin[l + 32 * i];
#pragma unroll
    for (int i = 0; i < 8; i++)
        ss += v[i].x * v[i].x + v[i].y * v[i].y + v[i].z * v[i].z + v[i].w * v[i].w;
#pragma unroll
    for (int o = 16; o; o >>= 1) ss += __shfl_xor_sync(0xffffffffu, ss, o);

    float sc = 1.0f / fmaxf(sqrtf(ss), 1e-12f);
#pragma unroll
    for (int i = 0; i < 8; i++) {
        uint2 w2;
        w2.x = packh2(v[i].x * sc, v[i].y * sc);
        w2.y = packh2(v[i].z * sc, v[i].w * sc);
        dst[l + 32 * i] = w2;
    }
    if (gw < B_ROWS && l == 0) g_rowsum[gw] = 0.0f;
}

// ---------------------------------------------------------------------------
// Kernel 2: f16 mma.sync GEMM (f16 accum), CTA 128x128, BK=64, 3-stage
// cp.async pipeline, 110.6KB smem -> 2 CTAs/SM (16 warps/SM).
// 8 warps: wm = wid>>2 (64 rows), wn = wid&3 (32 cols).
// NEW: fragment DOUBLE BUFFERING across ks (f16 accum frees 32 regs) —
// next-ks ldsm issues while current-ks mma occupies the tensor pipe.
// Epilogue: iso = |ds|*sqrt(max(1-sim,0)); store + row-sum atomics.
// ---------------------------------------------------------------------------
#define STAGES 3
#define BK 64
#define KCHUNKS (F_DIM / BK)          // 16
#define PAD_BYTES 144                 // (64+8) f16 per row
#define A_ST_BYTES (128 * PAD_BYTES)  // 18432
#define STAGE_BYTES (2 * A_ST_BYTES)  // 36864 (A then B)
#define GEMM_SMEM (STAGES * STAGE_BYTES)   // 110592 -> 2 CTAs/SM

__device__ __forceinline__ void load_tile(uint32_t base, int kc, int m0, int n0, int tid) {
    const char* fb = (const char*)g_Fb;
    const char* pb = (const char*)g_Pb;
    uint32_t st = base + (uint32_t)(kc % STAGES) * STAGE_BYTES;
#pragma unroll
    for (int it = 0; it < 4; it++) {
        int s = tid + it * 256;            // 0..1023
        int r = s >> 3, q = s & 7;
        cp_async16(st + (uint32_t)(r * PAD_BYTES + q * 16),
                   fb + (size_t)(m0 + r) * 2048 + (size_t)kc * 128 + q * 16);
    }
    uint32_t stB = st + A_ST_BYTES;
#pragma unroll
    for (int it = 0; it < 4; it++) {
        int s = tid + it * 256;
        int r = s >> 3, q = s & 7;
        cp_async16(stB + (uint32_t)(r * PAD_BYTES + q * 16),
                   pb + (size_t)(n0 + r) * 2048 + (size_t)kc * 128 + q * 16);
    }
    cp_commit();
}

// Load one ks-slice of fragments (4 A ldsm + 2 B ldsm), layout identical to
// the verified R4/R13 path.
__device__ __forceinline__ void load_frags(uint32_t (&a)[4][4], uint32_t (&b)[4][2],
                                           uint32_t aBase, uint32_t bBase,
                                           int ks, int g, int r8) {
#pragma unroll
    for (int mt = 0; mt < 4; mt++) {
        // lanes: g0 rows 0-7 k-lo | g1 rows 8-15 k-lo | g2 rows 0-7 k-hi | g3 rows 8-15 k-hi
        uint32_t addr = aBase + (uint32_t)((mt * 16 + (g & 1) * 8 + r8) * PAD_BYTES
                                          + ks * 32 + (g >> 1) * 16);
        ldsm_x4(a[mt][0], a[mt][1], a[mt][2], a[mt][3], addr);
    }
#pragma unroll
    for (int pair = 0; pair < 2; pair++) {
        // matrices: [ntile 2p, k-lo] [ntile 2p, k-hi] [ntile 2p+1, k-lo] [ntile 2p+1, k-hi]
        int ntile = pair * 2 + (g >> 1);
        uint32_t addr = bBase + (uint32_t)((ntile * 8 + r8) * PAD_BYTES
                                          + ks * 32 + (g & 1) * 16);
        ldsm_x4(b[pair * 2][0], b[pair * 2][1], b[pair * 2 + 1][0], b[pair * 2 + 1][1], addr);
    }
}

__global__ void __launch_bounds__(256, 2) gemm_kernel(const float* __restrict__ ds,
                                                      float* __restrict__ out) {
    extern __shared__ char smem_raw[];
    uint32_t base = smem_u32(smem_raw);

    int tid = threadIdx.x;
    int wid = tid >> 5, l = tid & 31;
    int wm = wid >> 2, wn = wid & 3;
    int m0 = blockIdx.y * 128, n0 = blockIdx.x * 128;

    // f16 accumulators: [mt][nt][2] b32 regs, each = half2
    uint32_t c[4][4][2];
#pragma unroll
    for (int i = 0; i < 4; i++)
#pragma unroll
        for (int j = 0; j < 4; j++) { c[i][j][0] = 0u; c[i][j][1] = 0u; }

    int g = l >> 3;          // 0..3
    int r8 = l & 7;

    // prologue: prefetch chunks 0, 1
    load_tile(base, 0, m0, n0, tid);
    load_tile(base, 1, m0, n0, tid);

    uint32_t fa[2][4][4], fb[2][4][2];   // ks ping-pong fragment buffers

    for (int kc = 0; kc < KCHUNKS; kc++) {
        if (kc < KCHUNKS - 1) asm volatile("cp.async.wait_group 1;" ::: "memory");
        else                  asm volatile("cp.async.wait_group 0;" ::: "memory");
        __syncthreads();

        if (kc + 2 < KCHUNKS) load_tile(base, kc + 2, m0, n0, tid);

        uint32_t st = base + (uint32_t)(kc % STAGES) * STAGE_BYTES;
        uint32_t aBase = st + (uint32_t)(wm * 64) * PAD_BYTES;
        uint32_t bBase = st + A_ST_BYTES + (uint32_t)(wn * 32) * PAD_BYTES;

        load_frags(fa[0], fb[0], aBase, bBase, 0, g, r8);
#pragma unroll
        for (int ks = 0; ks < 4; ks++) {
            int cur = ks & 1, nxt = cur ^ 1;
            if (ks < 3) load_frags(fa[nxt], fb[nxt], aBase, bBase, ks + 1, g, r8);
#pragma unroll
            for (int mt = 0; mt < 4; mt++)
#pragma unroll
                for (int nt = 0; nt < 4; nt++)
                    mma_f16(c[mt][nt][0], c[mt][nt][1],
                            fa[cur][mt][0], fa[cur][mt][1], fa[cur][mt][2], fa[cur][mt][3],
                            fb[cur][nt][0], fb[cur][nt][1]);
        }
        __syncthreads();
    }

    // ---------------- epilogue ----------------
    float dsa = fabsf(__ldg(ds));
    float rs[4][2];
#pragma unroll
    for (int mt = 0; mt < 4; mt++) { rs[mt][0] = 0.0f; rs[mt][1] = 0.0f; }

#pragma unroll
    for (int mt = 0; mt < 4; mt++) {
        int mrow = m0 + wm * 64 + mt * 16 + (l >> 2);
#pragma unroll
        for (int nt = 0; nt < 4; nt++) {
            int col = n0 + wn * 32 + nt * 8 + 2 * (l & 3);
            float2 p01 = __half22float2(*reinterpret_cast<__half2*>(&c[mt][nt][0]));
            float2 p23 = __half22float2(*reinterpret_cast<__half2*>(&c[mt][nt][1]));
            float i0 = dsa * sqrtf(fmaxf(1.0f - p01.x, 0.0f));
            float i1 = dsa * sqrtf(fmaxf(1.0f - p01.y, 0.0f));
            float i2 = dsa * sqrtf(fmaxf(1.0f - p23.x, 0.0f));
            float i3 = dsa * sqrtf(fmaxf(1.0f - p23.y, 0.0f));
            if (col < C_COLS) {             // col even, C_COLS even -> col+1 valid too
                rs[mt][0] += i0 + i1;
                rs[mt][1] += i2 + i3;
                *(float2*)(out + (size_t)mrow * C_COLS + col) = make_float2(i0, i1);
                *(float2*)(out + (size_t)(mrow + 8) * C_COLS + col) = make_float2(i2, i3);
            }
        }
    }
    // reduce row sums over the 4 lanes sharing a row (xor 1, 2), then atomics
#pragma unroll
    for (int mt = 0; mt < 4; mt++) {
#pragma unroll
        for (int h = 0; h < 2; h++) {
            float v = rs[mt][h];
            v += __shfl_xor_sync(0xffffffffu, v, 1);
            v += __shfl_xor_sync(0xffffffffu, v, 2);
            if ((l & 3) == 0) {
                int mrow = m0 + wm * 64 + mt * 16 + (l >> 2) + h * 8;
                atomicAdd(&g_rowsum[mrow], v);
            }
        }
    }
}

// ---------------------------------------------------------------------------
// Kernel 3: logits = -(iso + rowmean)/T, 2 float4 per thread (MLP=2).
// ---------------------------------------------------------------------------
#define F4_PER_ROW (C_COLS / 4)              // 250
#define FIN_TOTAL  (B_ROWS * F4_PER_ROW)     // 4,096,000
#define FIN_HALF   (FIN_TOTAL / 2)           // 2,048,000

__global__ void __launch_bounds__(256) finalize_kernel(float* __restrict__ out,
                                                       const float* __restrict__ temp) {
    unsigned v0 = blockIdx.x * 256u + threadIdx.x;
    if (v0 >= (unsigned)FIN_HALF) return;
    unsigned v1 = v0 + (unsigned)FIN_HALF;
    float invt = 1.0f / __ldg(temp);

    unsigned r0 = v0 / (unsigned)F4_PER_ROW;
    unsigned r1 = v1 / (unsigned)F4_PER_ROW;
    float4 x0 = *(float4*)(out + (size_t)v0 * 4);
    float4 x1 = *(float4*)(out + (size_t)v1 * 4);
    float m0 = __ldg(&g_rowsum[r0]) * (1.0f / (float)C_COLS);
    float m1 = __ldg(&g_rowsum[r1]) * (1.0f / (float)C_COLS);

    x0.x = -(x0.x + m0) * invt;  x0.y = -(x0.y + m0) * invt;
    x0.z = -(x0.z + m0) * invt;  x0.w = -(x0.w + m0) * invt;
    x1.x = -(x1.x + m1) * invt;  x1.y = -(x1.y + m1) * invt;
    x1.z = -(x1.z + m1) * invt;  x1.w = -(x1.w + m1) * invt;

    *(float4*)(out + (size_t)v0 * 4) = x0;
    *(float4*)(out + (size_t)v1 * 4) = x1;
}

// ---------------------------------------------------------------------------
extern "C" void kernel_launch(void* const* d_in, const int* in_sizes, int n_in,
                              void* d_out, int out_size) {
    const float* feat = (const float*)d_in[0];
    const float* prot = (const float*)d_in[1];
    const float* ds   = (const float*)d_in[2];
    const float* temp = (const float*)d_in[3];
    float* out = (float*)d_out;

    cudaFuncSetAttribute(gemm_kernel, cudaFuncAttributeMaxDynamicSharedMemorySize, GEMM_SMEM);

    norm_kernel<<<NORM_ROWS / 8, 256>>>(feat, prot);
    gemm_kernel<<<dim3(C_PAD / 128, B_ROWS / 128), 256, GEMM_SMEM>>>(ds, out);
    finalize_kernel<<<(FIN_HALF + 255) / 256, 256>>>(out, temp);
}